// round 1
// baseline (speedup 1.0000x reference)
#include <cuda_runtime.h>
#include <cstdint>

#define T_STEPS 512
#define BATCH   256
#define N1      512
#define N2      256
#define N3      64
#define N4      784

// Scratch (no allocations allowed): spike bitmasks, transposed W_lif, weighted spike sums.
__device__ uint32_t g_bits[T_STEPS * BATCH * 8];   // [t][b][8 words]  (4 MB)
__device__ float    g_WT[N2 * N1];                 // W_lif^T : [i][n] (512 KB)
__device__ float    g_S[BATCH * N1];               // weighted spike sums (512 KB)

// ---------------------------------------------------------------------------
// Kernel 1: pack binary spike train into bitmasks. One block per (t,b) row.
// ---------------------------------------------------------------------------
__global__ void pack_kernel(const float* __restrict__ spk) {
    int tb = blockIdx.x;              // t*BATCH + b
    int i  = threadIdx.x;             // 0..255 (input neuron)
    float v = spk[(size_t)tb * N2 + i];
    unsigned m = __ballot_sync(0xffffffffu, v > 0.5f);
    if ((i & 31) == 0) g_bits[tb * 8 + (i >> 5)] = m;
}

// ---------------------------------------------------------------------------
// Kernel 2: transpose W_lif [N1,N2] -> g_WT [N2,N1]
// ---------------------------------------------------------------------------
__global__ void transpose_kernel(const float* __restrict__ W) {
    __shared__ float tile[32][33];
    int bi = blockIdx.x;    // tile along i (N2): 8 tiles
    int bn = blockIdx.y;    // tile along n (N1): 16 tiles
    int tx = threadIdx.x, ty = threadIdx.y;
    #pragma unroll
    for (int r = ty; r < 32; r += 8)
        tile[r][tx] = W[(bn * 32 + r) * N2 + bi * 32 + tx];   // [n-local r][i-local tx]
    __syncthreads();
    #pragma unroll
    for (int r = ty; r < 32; r += 8)
        g_WT[(bi * 32 + r) * N1 + bn * 32 + tx] = tile[tx][r];
}

// ---------------------------------------------------------------------------
// Kernel 3: fused sparse-current + LIF scan + weighted spike accumulation.
// Block = (n-chunk of 64 neurons) x (8 batches). Warp = 1 batch x 64 neurons
// (float2 per lane). W slice (256 x 64 fp32 = 64 KB) lives in smem.
// ---------------------------------------------------------------------------
__global__ void __launch_bounds__(256, 3) scan_kernel(const float* __restrict__ b_lif) {
    extern __shared__ float Ws[];                   // [256][64]
    const int nchunk = blockIdx.x & 7;
    const int bchunk = blockIdx.x >> 3;
    const int tid  = threadIdx.x;
    const int warp = tid >> 5, lane = tid & 31;
    const int b     = bchunk * 8 + warp;
    const int nbase = nchunk * 64;

    // Load W slice: Ws[i*64 + nl] = W_lif^T[i][nbase+nl]  (coalesced, conflict-free)
    #pragma unroll 4
    for (int idx = tid; idx < N2 * 64; idx += 256) {
        int i = idx >> 6, nl = idx & 63;
        Ws[idx] = g_WT[i * N1 + nbase + nl];
    }
    __syncthreads();

    const int n0 = nbase + lane * 2;
    const float2 bl = *reinterpret_cast<const float2*>(b_lif + n0);

    float mx = 0.0f, my = 0.0f;     // LIF membrane (2 neurons / lane)
    float Sx = 0.0f, Sy = 0.0f;     // weighted spike sums

    // p = beta_li^T = 0.95^512 via 9 squarings (T = 2^9)
    float p = 0.95f;
    #pragma unroll
    for (int k = 0; k < 9; k++) p *= p;
    const float inv_beta = 1.0f / 0.95f;
    const float wnorm    = 1.0f / 25.6f;            // 1 / (T * (1-beta_li))

    for (int t = 0; t < T_STEPS; t++) {
        const uint4* row =
            reinterpret_cast<const uint4*>(g_bits) + (size_t)(t * BATCH + b) * 2;
        uint4 wa = row[0];
        uint4 wb = row[1];
        float cx = bl.x, cy = bl.y;                 // cur = b_lif + sparse sum
        uint32_t words[8] = {wa.x, wa.y, wa.z, wa.w, wb.x, wb.y, wb.z, wb.w};
        #pragma unroll
        for (int w = 0; w < 8; w++) {
            uint32_t m = words[w];
            const float2* base = reinterpret_cast<const float2*>(Ws) + w * 1024 + lane;
            while (m) {
                int i = __ffs(m) - 1;
                m &= m - 1;
                float2 wv = base[i * 32];           // LDS.64, contiguous across warp
                cx += wv.x;
                cy += wv.y;
            }
        }
        // snntorch Leaky, reset_mechanism='subtract' (reset from previous mem)
        float rx = mx > 1.0f ? 1.0f : 0.0f;
        float ry = my > 1.0f ? 1.0f : 0.0f;
        mx = 0.9f * mx + cx - rx;
        my = 0.9f * my + cy - ry;
        float wt = (1.0f - p) * wnorm;              // w_t = (1-beta^{T-t})/(T(1-beta))
        if (mx > 1.0f) Sx += wt;
        if (my > 1.0f) Sy += wt;
        p *= inv_beta;
    }
    float2 Sv = make_float2(Sx, Sy);
    *reinterpret_cast<float2*>(g_S + b * N1 + n0) = Sv;
}

// ---------------------------------------------------------------------------
// Kernel 4: tail — x = S @ W_li^T + SW*b_li ; h = relu(x@W1^T+b1) ;
//           y = h@W2^T+b2 ; layernorm. One block per batch row.
// ---------------------------------------------------------------------------
__global__ void __launch_bounds__(256) tail_kernel(
    const float* __restrict__ W_li, const float* __restrict__ b_li,
    const float* __restrict__ W1,  const float* __restrict__ b1,
    const float* __restrict__ W2,  const float* __restrict__ b2,
    const float* __restrict__ ln_g, const float* __restrict__ ln_b,
    float* __restrict__ out)
{
    __shared__ float sS[N1];
    __shared__ float sx[N2];
    __shared__ float sh[N3];
    __shared__ float sy[N4];
    __shared__ float sred[16];
    const int b = blockIdx.x, tid = threadIdx.x;

    sS[tid]       = g_S[b * N1 + tid];
    sS[tid + 256] = g_S[b * N1 + 256 + tid];
    __syncthreads();

    // SW = sum_t w_t = (T - beta(1-beta^T)/(1-beta)) / (T(1-beta))
    float p = 0.95f;
    #pragma unroll
    for (int k = 0; k < 9; k++) p *= p;
    const float SW = (512.0f - 19.0f * (1.0f - p)) / 25.6f;

    // x[tid] = SW*b_li[tid] + dot(S_row, W_li[tid,:])
    {
        float acc = SW * b_li[tid];
        const float4* wrow = reinterpret_cast<const float4*>(W_li + tid * N1);
        const float4* sp   = reinterpret_cast<const float4*>(sS);
        #pragma unroll 4
        for (int i = 0; i < N1 / 4; i++) {
            float4 wv = wrow[i], sv = sp[i];
            acc += wv.x * sv.x + wv.y * sv.y + wv.z * sv.z + wv.w * sv.w;
        }
        sx[tid] = acc;
    }
    __syncthreads();

    if (tid < N3) {
        float acc = b1[tid];
        const float4* wrow = reinterpret_cast<const float4*>(W1 + tid * N2);
        const float4* xp   = reinterpret_cast<const float4*>(sx);
        #pragma unroll 4
        for (int i = 0; i < N2 / 4; i++) {
            float4 wv = wrow[i], xv = xp[i];
            acc += wv.x * xv.x + wv.y * xv.y + wv.z * xv.z + wv.w * xv.w;
        }
        sh[tid] = fmaxf(acc, 0.0f);
    }
    __syncthreads();

    for (int k = tid; k < N4; k += 256) {
        float acc = b2[k];
        const float4* wr = reinterpret_cast<const float4*>(W2 + k * N3);
        const float4* hp = reinterpret_cast<const float4*>(sh);
        #pragma unroll
        for (int j = 0; j < N3 / 4; j++) {
            float4 wv = wr[j], hv = hp[j];
            acc += wv.x * hv.x + wv.y * hv.y + wv.z * hv.z + wv.w * hv.w;
        }
        sy[k] = acc;
    }
    __syncthreads();

    // mean
    float s = 0.0f;
    for (int k = tid; k < N4; k += 256) s += sy[k];
    #pragma unroll
    for (int o = 16; o > 0; o >>= 1) s += __shfl_xor_sync(0xffffffffu, s, o);
    if ((tid & 31) == 0) sred[tid >> 5] = s;
    __syncthreads();
    if (tid < 32) {
        float v = (tid < 8) ? sred[tid] : 0.0f;
        #pragma unroll
        for (int o = 4; o > 0; o >>= 1) v += __shfl_xor_sync(0xffffffffu, v, o);
        if (tid == 0) sred[0] = v;
    }
    __syncthreads();
    const float mu = sred[0] / (float)N4;
    __syncthreads();   // all mu reads done before sred is reused

    // variance (two-pass)
    float s2 = 0.0f;
    for (int k = tid; k < N4; k += 256) { float d = sy[k] - mu; s2 += d * d; }
    #pragma unroll
    for (int o = 16; o > 0; o >>= 1) s2 += __shfl_xor_sync(0xffffffffu, s2, o);
    if ((tid & 31) == 0) sred[tid >> 5] = s2;
    __syncthreads();
    if (tid < 32) {
        float v = (tid < 8) ? sred[tid] : 0.0f;
        #pragma unroll
        for (int o = 4; o > 0; o >>= 1) v += __shfl_xor_sync(0xffffffffu, v, o);
        if (tid == 0) sred[0] = v;
    }
    __syncthreads();
    const float var  = sred[0] / (float)N4;
    const float rstd = 1.0f / sqrtf(var + 1e-5f);

    for (int k = tid; k < N4; k += 256)
        out[(size_t)b * N4 + k] = (sy[k] - mu) * rstd * ln_g[k] + ln_b[k];
}

// ---------------------------------------------------------------------------
extern "C" void kernel_launch(void* const* d_in, const int* in_sizes, int n_in,
                              void* d_out, int out_size) {
    const float* spk   = (const float*)d_in[0];
    const float* W_lif = (const float*)d_in[1];
    const float* b_lif = (const float*)d_in[2];
    const float* W_li  = (const float*)d_in[3];
    const float* b_li  = (const float*)d_in[4];
    const float* W1    = (const float*)d_in[5];
    const float* b1    = (const float*)d_in[6];
    const float* W2    = (const float*)d_in[7];
    const float* b2    = (const float*)d_in[8];
    const float* ln_g  = (const float*)d_in[9];
    const float* ln_b  = (const float*)d_in[10];
    float* out = (float*)d_out;

    cudaFuncSetAttribute(scan_kernel, cudaFuncAttributeMaxDynamicSharedMemorySize, 65536);

    pack_kernel<<<T_STEPS * BATCH, 256>>>(spk);
    transpose_kernel<<<dim3(8, 16), dim3(32, 8)>>>(W_lif);
    scan_kernel<<<256, 256, 65536>>>(b_lif);
    tail_kernel<<<BATCH, 256>>>(W_li, b_li, W1, b1, W2, b2, ln_g, ln_b, out);
}

// round 2
// speedup vs baseline: 2.2285x; 2.2285x over previous
#include <cuda_runtime.h>
#include <cstdint>

#define T_STEPS 512
#define BATCH   256
#define N1      512
#define N2      256
#define N3      64
#define N4      784

// Scratch (no allocations allowed)
__device__ int      g_cnt[T_STEPS * BATCH];          // spike count per (t,b)
__device__ uint4    g_idx4[T_STEPS * BATCH * 4];     // 64 byte-indices per (t,b), zero-padded (8 MB)
__device__ float    g_WT[N2 * N1];                   // W_lif^T : [i][n] (512 KB)
__device__ float    g_S[BATCH * N1];                 // weighted spike sums
__device__ float    g_x[BATCH * N2];                 // LI-mean @ W_li^T output

// ---------------------------------------------------------------------------
// Kernel 1: pack spikes into per-(t,b) byte index lists + counts.
// One warp per (t,b) row; 4 warps per block.
// ---------------------------------------------------------------------------
__global__ void __launch_bounds__(128) pack_kernel(const float* __restrict__ spk) {
    const int warp = threadIdx.x >> 5, lane = threadIdx.x & 31;
    const int tb = blockIdx.x * 4 + warp;
    const float* row = spk + (size_t)tb * N2;

    uint32_t mw[8];
    #pragma unroll
    for (int w = 0; w < 8; w++) {
        float v = row[w * 32 + lane];
        mw[w] = __ballot_sync(0xffffffffu, v > 0.5f);
    }

    // zero-fill the 64-byte index slot (padding = index 0)
    uint32_t* idx32 = reinterpret_cast<uint32_t*>(g_idx4) + (size_t)tb * 16;
    if (lane < 16) idx32[lane] = 0u;
    __syncwarp();

    // lane k (k<8) owns mask word k
    uint32_t myw = 0;
    #pragma unroll
    for (int k = 0; k < 8; k++) myw = (lane == k) ? mw[k] : myw;
    int c = (lane < 8) ? __popc(myw) : 0;

    // inclusive prefix over lanes 0..7
    int off = c;
    #pragma unroll
    for (int d = 1; d < 8; d <<= 1) {
        int o = __shfl_up_sync(0xffffffffu, off, d);
        if (lane >= d) off += o;
    }
    const int excl  = off - c;
    const int total = __shfl_sync(0xffffffffu, off, 7);

    if (lane < 8) {
        uint32_t m = myw;
        int p = excl;
        uint8_t* dst = reinterpret_cast<uint8_t*>(g_idx4) + (size_t)tb * 64;
        while (m) {
            int i = __ffs(m) - 1;
            m &= m - 1;
            if (p < 64) dst[p] = (uint8_t)(lane * 32 + i);
            p++;
        }
    }
    if (lane == 0) g_cnt[tb] = min(total, 64);
}

// ---------------------------------------------------------------------------
// Kernel 2: transpose W_lif [N1,N2] -> g_WT [N2,N1]
// ---------------------------------------------------------------------------
__global__ void transpose_kernel(const float* __restrict__ W) {
    __shared__ float tile[32][33];
    int bi = blockIdx.x;    // tile along i (N2): 8 tiles
    int bn = blockIdx.y;    // tile along n (N1): 16 tiles
    int tx = threadIdx.x, ty = threadIdx.y;
    #pragma unroll
    for (int r = ty; r < 32; r += 8)
        tile[r][tx] = W[(bn * 32 + r) * N2 + bi * 32 + tx];
    __syncthreads();
    #pragma unroll
    for (int r = ty; r < 32; r += 8)
        g_WT[(bi * 32 + r) * N1 + bn * 32 + tx] = tile[tx][r];
}

// ---------------------------------------------------------------------------
// Kernel 3: fused sparse-current + LIF scan + weighted spike accumulation.
// Block = 64 neurons x 16 batches (512 threads), grid = 8 nchunks x 16 bchunks.
// Warp = 1 batch x 64 neurons (float2/lane). W slice (256x64 fp32) in smem.
// Inner loop: 7 unconditional groups of 4 independent LDS.64 (index-0 padded,
// compensated), 1 guarded group, rare gmem loop for n>32.
// ---------------------------------------------------------------------------
__global__ void __launch_bounds__(512, 1) scan_kernel(const float* __restrict__ b_lif) {
    extern __shared__ float Ws[];                   // [256][64] floats
    const int nchunk = blockIdx.x & 7;
    const int bchunk = blockIdx.x >> 3;
    const int tid  = threadIdx.x;
    const int warp = tid >> 5, lane = tid & 31;
    const int b     = bchunk * 16 + warp;
    const int nbase = nchunk * 64;

    for (int idx = tid; idx < N2 * 64; idx += 512) {
        int i = idx >> 6, nl = idx & 63;
        Ws[idx] = g_WT[i * N1 + nbase + nl];
    }
    __syncthreads();

    const float2* WsF2 = reinterpret_cast<const float2*>(Ws);
    const int n0 = nbase + lane * 2;
    const float2 bl = *reinterpret_cast<const float2*>(b_lif + n0);
    const float2 W0 = WsF2[lane];                   // row 0 (padding compensation)

    float mx = 0.0f, my = 0.0f;
    float Sx = 0.0f, Sy = 0.0f;

    float p = 0.95f;                                // beta_li^T via 9 squarings
    #pragma unroll
    for (int k = 0; k < 9; k++) p *= p;
    const float inv_beta = 1.0f / 0.95f;
    const float wnorm    = 1.0f / 25.6f;

    const uint32_t* idxU = reinterpret_cast<const uint32_t*>(g_idx4);

    // prefetch t=0
    int  n_nx = g_cnt[b];
    uint4 a_nx = g_idx4[(size_t)b * 4 + 0];
    uint4 b_nx = g_idx4[(size_t)b * 4 + 1];

    for (int t = 0; t < T_STEPS; t++) {
        const int n = n_nx;
        const uint32_t w0 = a_nx.x, w1 = a_nx.y, w2 = a_nx.z, w3 = a_nx.w;
        const uint32_t w4 = b_nx.x, w5 = b_nx.y, w6 = b_nx.z, w7 = b_nx.w;

        if (t < T_STEPS - 1) {                       // prefetch t+1
            const size_t tbn = (size_t)(t + 1) * BATCH + b;
            n_nx = g_cnt[tbn];
            a_nx = g_idx4[tbn * 4 + 0];
            b_nx = g_idx4[tbn * 4 + 1];
        }

        float cx = bl.x, cy = bl.y;

        // 7 unconditional groups (28 slots), zero-index padded
        #define GROUP_FULL(WW)                                              \
        {                                                                   \
            float2 v0 = WsF2[(((WW)      ) & 255u) * 32 + lane];            \
            float2 v1 = WsF2[(((WW) >>  8) & 255u) * 32 + lane];            \
            float2 v2 = WsF2[(((WW) >> 16) & 255u) * 32 + lane];            \
            float2 v3 = WsF2[ ((WW) >> 24)         * 32 + lane];            \
            cx += (v0.x + v1.x) + (v2.x + v3.x);                            \
            cy += (v0.y + v1.y) + (v2.y + v3.y);                            \
        }
        GROUP_FULL(w0) GROUP_FULL(w1) GROUP_FULL(w2) GROUP_FULL(w3)
        GROUP_FULL(w4) GROUP_FULL(w5) GROUP_FULL(w6)
        #undef GROUP_FULL

        // compensate padding (pads hit row 0)
        {
            float padf = (float)(28 - min(n, 28));
            cx = fmaf(padf, -W0.x, cx);
            cy = fmaf(padf, -W0.y, cy);
        }

        if (n > 28) {                                 // group 7 (value-zeroed remainder)
            int rem = n - 28;
            float2 v0 = WsF2[((w7      ) & 255u) * 32 + lane];
            float2 v1 = WsF2[((w7 >>  8) & 255u) * 32 + lane];
            float2 v2 = WsF2[((w7 >> 16) & 255u) * 32 + lane];
            float2 v3 = WsF2[ (w7 >> 24)         * 32 + lane];
            if (rem < 2) { v1.x = 0.f; v1.y = 0.f; }
            if (rem < 3) { v2.x = 0.f; v2.y = 0.f; }
            if (rem < 4) { v3.x = 0.f; v3.y = 0.f; }
            cx += (v0.x + v1.x) + (v2.x + v3.x);
            cy += (v0.y + v1.y) + (v2.y + v3.y);

            // rare overflow: n > 32 (~6% of steps)
            for (int g = 8; g * 4 < n; g++) {
                uint32_t ww = idxU[(size_t)(t * BATCH + b) * 16 + g];
                int r2 = n - g * 4;
                float2 u0 = WsF2[((ww      ) & 255u) * 32 + lane];
                float2 u1 = WsF2[((ww >>  8) & 255u) * 32 + lane];
                float2 u2 = WsF2[((ww >> 16) & 255u) * 32 + lane];
                float2 u3 = WsF2[ (ww >> 24)         * 32 + lane];
                if (r2 < 2) { u1.x = 0.f; u1.y = 0.f; }
                if (r2 < 3) { u2.x = 0.f; u2.y = 0.f; }
                if (r2 < 4) { u3.x = 0.f; u3.y = 0.f; }
                cx += (u0.x + u1.x) + (u2.x + u3.x);
                cy += (u0.y + u1.y) + (u2.y + u3.y);
            }
        }

        // LIF membrane (subtract reset from previous-step mem)
        float rx = (mx > 1.0f) ? 1.0f : 0.0f;
        float ry = (my > 1.0f) ? 1.0f : 0.0f;
        mx = 0.9f * mx + cx - rx;
        my = 0.9f * my + cy - ry;
        float wt = (1.0f - p) * wnorm;
        if (mx > 1.0f) Sx += wt;
        if (my > 1.0f) Sy += wt;
        p *= inv_beta;
    }
    *reinterpret_cast<float2*>(g_S + b * N1 + n0) = make_float2(Sx, Sy);
}

// ---------------------------------------------------------------------------
// Kernel 4a: x = S @ W_li^T + SW*b_li   (tiled smem GEMM, 256x256x512)
// ---------------------------------------------------------------------------
__global__ void __launch_bounds__(256) tailx_kernel(const float* __restrict__ W_li,
                                                    const float* __restrict__ b_li) {
    __shared__ float Stile[64][33];
    __shared__ float Wtile[64][33];
    const int bj = blockIdx.x & 3;
    const int bb = blockIdx.x >> 2;
    const int tx = threadIdx.x & 15, ty = threadIdx.x >> 4;

    float acc[4][4] = {};
    for (int k0 = 0; k0 < N1; k0 += 32) {
        for (int l = threadIdx.x; l < 64 * 32; l += 256) {
            int r = l >> 5, c = l & 31;
            Stile[r][c] = g_S[(bb * 64 + r) * N1 + k0 + c];
            Wtile[r][c] = W_li[(bj * 64 + r) * N1 + k0 + c];
        }
        __syncthreads();
        #pragma unroll
        for (int kk = 0; kk < 32; kk++) {
            float sreg[4], wreg[4];
            #pragma unroll
            for (int r = 0; r < 4; r++) sreg[r] = Stile[ty * 4 + r][kk];
            #pragma unroll
            for (int c = 0; c < 4; c++) wreg[c] = Wtile[tx * 4 + c][kk];
            #pragma unroll
            for (int r = 0; r < 4; r++)
                #pragma unroll
                for (int c = 0; c < 4; c++) acc[r][c] += sreg[r] * wreg[c];
        }
        __syncthreads();
    }

    float pw = 0.95f;
    #pragma unroll
    for (int k = 0; k < 9; k++) pw *= pw;
    const float SW = (512.0f - 19.0f * (1.0f - pw)) / 25.6f;

    #pragma unroll
    for (int r = 0; r < 4; r++) {
        int brow = bb * 64 + ty * 4 + r;
        #pragma unroll
        for (int c = 0; c < 4; c++) {
            int j = bj * 64 + tx * 4 + c;
            g_x[brow * N2 + j] = acc[r][c] + SW * b_li[j];
        }
    }
}

// ---------------------------------------------------------------------------
// Kernel 4b: per-batch MLP + layernorm (coalesced warp-per-output reductions)
// ---------------------------------------------------------------------------
__global__ void __launch_bounds__(256) tailmlp_kernel(
    const float* __restrict__ W1,  const float* __restrict__ b1,
    const float* __restrict__ W2,  const float* __restrict__ b2,
    const float* __restrict__ ln_g, const float* __restrict__ ln_b,
    float* __restrict__ out)
{
    __shared__ float sx[N2];
    __shared__ float sh[N3];
    __shared__ float sy[N4];
    __shared__ float sred[16];
    const int b = blockIdx.x, tid = threadIdx.x;
    const int warp = tid >> 5, lane = tid & 31;

    sx[tid] = g_x[b * N2 + tid];
    __syncthreads();

    // h[o] = relu(W1[o,:] . x + b1[o]) — warp computes 8 outputs, lanes over k
    #pragma unroll
    for (int oo = 0; oo < 8; oo++) {
        int o = warp * 8 + oo;
        float acc = 0.0f;
        #pragma unroll
        for (int kk = 0; kk < 8; kk++) {
            int k = kk * 32 + lane;
            acc += W1[o * N2 + k] * sx[k];
        }
        #pragma unroll
        for (int d = 16; d > 0; d >>= 1) acc += __shfl_xor_sync(0xffffffffu, acc, d);
        if (lane == 0) sh[o] = fmaxf(acc + b1[o], 0.0f);
    }
    __syncthreads();

    // y[o] = W2[o,:] . h + b2[o] — warp-per-output, float2/lane
    for (int g = 0; g < 98; g++) {
        int o = warp + g * 8;
        const float2* w2 = reinterpret_cast<const float2*>(W2 + o * N3);
        const float2* hh = reinterpret_cast<const float2*>(sh);
        float2 wv = w2[lane], hv = hh[lane];
        float acc = wv.x * hv.x + wv.y * hv.y;
        #pragma unroll
        for (int d = 16; d > 0; d >>= 1) acc += __shfl_xor_sync(0xffffffffu, acc, d);
        if (lane == 0) sy[o] = acc + b2[o];
    }
    __syncthreads();

    // layernorm over 784
    float s = 0.0f;
    for (int k = tid; k < N4; k += 256) s += sy[k];
    #pragma unroll
    for (int o = 16; o > 0; o >>= 1) s += __shfl_xor_sync(0xffffffffu, s, o);
    if (lane == 0) sred[warp] = s;
    __syncthreads();
    if (tid < 32) {
        float v = (tid < 8) ? sred[tid] : 0.0f;
        #pragma unroll
        for (int o = 4; o > 0; o >>= 1) v += __shfl_xor_sync(0xffffffffu, v, o);
        if (tid == 0) sred[0] = v;
    }
    __syncthreads();
    const float mu = sred[0] / (float)N4;
    __syncthreads();

    float s2 = 0.0f;
    for (int k = tid; k < N4; k += 256) { float d = sy[k] - mu; s2 += d * d; }
    #pragma unroll
    for (int o = 16; o > 0; o >>= 1) s2 += __shfl_xor_sync(0xffffffffu, s2, o);
    if (lane == 0) sred[warp] = s2;
    __syncthreads();
    if (tid < 32) {
        float v = (tid < 8) ? sred[tid] : 0.0f;
        #pragma unroll
        for (int o = 4; o > 0; o >>= 1) v += __shfl_xor_sync(0xffffffffu, v, o);
        if (tid == 0) sred[0] = v;
    }
    __syncthreads();
    const float var  = sred[0] / (float)N4;
    const float rstd = rsqrtf(var + 1e-5f);

    for (int k = tid; k < N4; k += 256)
        out[(size_t)b * N4 + k] = (sy[k] - mu) * rstd * ln_g[k] + ln_b[k];
}

// ---------------------------------------------------------------------------
extern "C" void kernel_launch(void* const* d_in, const int* in_sizes, int n_in,
                              void* d_out, int out_size) {
    const float* spk   = (const float*)d_in[0];
    const float* W_lif = (const float*)d_in[1];
    const float* b_lif = (const float*)d_in[2];
    const float* W_li  = (const float*)d_in[3];
    const float* b_li  = (const float*)d_in[4];
    const float* W1    = (const float*)d_in[5];
    const float* b1    = (const float*)d_in[6];
    const float* W2    = (const float*)d_in[7];
    const float* b2    = (const float*)d_in[8];
    const float* ln_g  = (const float*)d_in[9];
    const float* ln_b  = (const float*)d_in[10];
    float* out = (float*)d_out;

    cudaFuncSetAttribute(scan_kernel, cudaFuncAttributeMaxDynamicSharedMemorySize, 65536);

    pack_kernel<<<T_STEPS * BATCH / 4, 128>>>(spk);
    transpose_kernel<<<dim3(8, 16), dim3(32, 8)>>>(W_lif);
    scan_kernel<<<128, 512, 65536>>>(b_lif);
    tailx_kernel<<<16, 256>>>(W_li, b_li);
    tailmlp_kernel<<<BATCH, 256>>>(W1, b1, W2, b2, ln_g, ln_b, out);
}